// round 1
// baseline (speedup 1.0000x reference)
#include <cuda_runtime.h>
#include <cstdint>

#define N_PTS   10242
#define C_DIM   64
#define K_DIM   9
#define NBR_DIM 7
#define O_DIM   64
#define BT_DIM  16
#define M_TOTAL (BT_DIM * N_PTS)     /* 163872 */
#define CK_DIM  (C_DIM * K_DIM)      /* 576    */

// Scratch (static __device__ arrays — no runtime allocation)
__device__ float g_itp[(size_t)M_TOTAL * CK_DIM];   // A matrix, [m][k*64+c]
__device__ float g_W2[CK_DIM * O_DIM];              // W2[(k*64+c)*64 + o]
__device__ int   g_is64;

// ---------------------------------------------------------------------------
// Detect whether `index` arrived as int64 or int32. For int64 data (values
// < 2^31), every odd int32 word is the zero high-word. For genuine int32
// data (71694 random values in [0,10242)), 35847 consecutive zeros at odd
// positions is impossible.
// ---------------------------------------------------------------------------
__global__ void detect_idx_kernel(const int* __restrict__ idx32) {
    __shared__ int s_any;
    if (threadIdx.x == 0) s_any = 0;
    __syncthreads();
    int any = 0;
    const int pairs = N_PTS * NBR_DIM / 2;   // 35847
    for (int i = threadIdx.x; i < pairs; i += blockDim.x)
        any |= (idx32[2 * i + 1] != 0);
    if (any) s_any = 1;
    __syncthreads();
    if (threadIdx.x == 0) g_is64 = (s_any == 0);
}

// ---------------------------------------------------------------------------
// Prepack W2[(k*64+c)][o] = conv_w[o, c, 0, k]   (conv_w flat: o*576 + c*9 + k)
// ---------------------------------------------------------------------------
__global__ void prepack_w_kernel(const float* __restrict__ conv_w) {
    int i = blockIdx.x * 256 + threadIdx.x;
    if (i >= CK_DIM * O_DIM) return;
    int o  = i & 63;
    int cc = i >> 6;        // k*64 + c
    int c  = cc & 63;
    int k  = cc >> 6;
    g_W2[i] = conv_w[(o * 64 + c) * 9 + k];
}

// ---------------------------------------------------------------------------
// Phase 1: itp[m, k*64+c] = sum_j x[bt, idx[n,j], c] * itp_mat[n, j, k]
// Block: 256 threads = 4 points x 64 channels. Gathers are 256B-coalesced.
// ---------------------------------------------------------------------------
__global__ void interp_kernel(const float* __restrict__ x,
                              const void*  __restrict__ index_raw,
                              const float* __restrict__ itp_mat) {
    __shared__ float sT[4][NBR_DIM * K_DIM];
    __shared__ int   sIdx[4][NBR_DIM];
    const int tid = threadIdx.x;
    const int m0  = blockIdx.x * 4;
    const int is64 = g_is64;

    for (int i = tid; i < 4 * 63; i += 256) {
        int mi = i / 63, e = i - mi * 63;
        int n = (m0 + mi) % N_PTS;
        sT[mi][e] = itp_mat[n * 63 + e];
    }
    if (tid < 4 * NBR_DIM) {
        int mi = tid / NBR_DIM, j = tid - mi * NBR_DIM;
        int n = (m0 + mi) % N_PTS;
        int v;
        if (is64) v = (int)((const long long*)index_raw)[n * NBR_DIM + j];
        else      v = ((const int*)index_raw)[n * NBR_DIM + j];
        sIdx[mi][j] = v;
    }
    __syncthreads();

    const int c    = tid & 63;
    const int mloc = tid >> 6;
    const int m    = m0 + mloc;                 // grid is exact: m < M_TOTAL
    const int bt   = m / N_PTS;
    const float* xb = x + (size_t)bt * N_PTS * C_DIM;

    float acc[K_DIM];
#pragma unroll
    for (int k = 0; k < K_DIM; k++) acc[k] = 0.f;

#pragma unroll
    for (int j = 0; j < NBR_DIM; j++) {
        float v = __ldg(xb + (size_t)sIdx[mloc][j] * C_DIM + c);
        const float* tj = &sT[mloc][j * K_DIM];
#pragma unroll
        for (int k = 0; k < K_DIM; k++) acc[k] = fmaf(v, tj[k], acc[k]);
    }

    float* dst = g_itp + (size_t)m * CK_DIM + c;
#pragma unroll
    for (int k = 0; k < K_DIM; k++) dst[k * 64] = acc[k];   // coalesced
}

// ---------------------------------------------------------------------------
// Phase 2: Out[m,o] = sum_cc A[m,cc] * W2[cc,o] + b[o]
// CTA tile 128x64, 9 K-chunks of 64 (chunk kc == filter tap k).
// 256 threads, micro-tile 4m x 8o. A transposed into smem with XOR swizzle:
// reads are conflict-free LDS.128, stores ~2-way.
// ---------------------------------------------------------------------------
#define BM     128
#define SA_LD  132
#define SWZ(kk) ((((kk) >> 1) & 7) << 2)

__global__ void gemm_kernel(const float* __restrict__ conv_b,
                            float* __restrict__ out) {
    extern __shared__ float smem[];
    float* sA = smem;                  // [64][SA_LD] transposed A (kk-major)
    float* sB = smem + 64 * SA_LD;     // [64][64]    W chunk (kk-major)

    const int tid = threadIdx.x;
    const int tm  = tid & 31;          // row group: rows tm*4 .. tm*4+3
    const int to  = tid >> 5;          // col group: cols to*8 .. to*8+7
    const int m0  = blockIdx.x * BM;

    float acc[4][8];
#pragma unroll
    for (int i = 0; i < 4; i++)
#pragma unroll
        for (int j = 0; j < 8; j++) acc[i][j] = 0.f;

    for (int kc = 0; kc < 9; kc++) {
        // --- load A tile (128 rows x 64 cols), store transposed+swizzled ---
#pragma unroll
        for (int i = 0; i < 8; i++) {
            int f4  = tid + i * 256;
            int row = f4 >> 4;
            int c4  = (f4 & 15) << 2;
            int m   = m0 + row;
            float4 v = make_float4(0.f, 0.f, 0.f, 0.f);
            if (m < M_TOTAL)
                v = *(const float4*)(g_itp + (size_t)m * CK_DIM + kc * 64 + c4);
            sA[(c4 + 0) * SA_LD + (row ^ SWZ(c4 + 0))] = v.x;
            sA[(c4 + 1) * SA_LD + (row ^ SWZ(c4 + 1))] = v.y;
            sA[(c4 + 2) * SA_LD + (row ^ SWZ(c4 + 2))] = v.z;
            sA[(c4 + 3) * SA_LD + (row ^ SWZ(c4 + 3))] = v.w;
        }
        // --- load B tile (64 kk x 64 o), straight float4 copies ---
#pragma unroll
        for (int i = 0; i < 4; i++) {
            int f4 = tid + i * 256;
            *(float4*)(sB + f4 * 4) =
                *(const float4*)(g_W2 + kc * 64 * 64 + f4 * 4);
        }
        __syncthreads();

#pragma unroll 8
        for (int kk = 0; kk < 64; kk++) {
            const float4 a  = *(const float4*)(sA + kk * SA_LD + ((tm * 4) ^ SWZ(kk)));
            const float4 b0 = *(const float4*)(sB + kk * 64 + to * 8);
            const float4 b1 = *(const float4*)(sB + kk * 64 + to * 8 + 4);
            float av[4] = {a.x, a.y, a.z, a.w};
            float bv[8] = {b0.x, b0.y, b0.z, b0.w, b1.x, b1.y, b1.z, b1.w};
#pragma unroll
            for (int i = 0; i < 4; i++)
#pragma unroll
                for (int j = 0; j < 8; j++)
                    acc[i][j] = fmaf(av[i], bv[j], acc[i][j]);
        }
        __syncthreads();
    }

    // --- epilogue: add bias, store ---
    float bias[8];
#pragma unroll
    for (int j = 0; j < 8; j++) bias[j] = __ldg(conv_b + to * 8 + j);
#pragma unroll
    for (int i = 0; i < 4; i++) {
        int m = m0 + tm * 4 + i;
        if (m < M_TOTAL) {
            float4 r0, r1;
            r0.x = acc[i][0] + bias[0];  r0.y = acc[i][1] + bias[1];
            r0.z = acc[i][2] + bias[2];  r0.w = acc[i][3] + bias[3];
            r1.x = acc[i][4] + bias[4];  r1.y = acc[i][5] + bias[5];
            r1.z = acc[i][6] + bias[6];  r1.w = acc[i][7] + bias[7];
            *(float4*)(out + (size_t)m * 64 + to * 8)     = r0;
            *(float4*)(out + (size_t)m * 64 + to * 8 + 4) = r1;
        }
    }
}

// ---------------------------------------------------------------------------
extern "C" void kernel_launch(void* const* d_in, const int* in_sizes, int n_in,
                              void* d_out, int out_size) {
    const float* x        = (const float*)d_in[0];
    const void*  index    = d_in[1];
    const float* itp_mat  = (const float*)d_in[2];
    const float* conv_w   = (const float*)d_in[3];
    const float* conv_b   = (const float*)d_in[4];
    float*       out      = (float*)d_out;

    detect_idx_kernel<<<1, 256>>>((const int*)index);
    prepack_w_kernel<<<(CK_DIM * O_DIM + 255) / 256, 256>>>(conv_w);
    interp_kernel<<<M_TOTAL / 4, 256>>>(x, index, itp_mat);

    const int smem_bytes = (64 * SA_LD + 64 * 64) * (int)sizeof(float);  // 50176
    cudaFuncSetAttribute(gemm_kernel,
                         cudaFuncAttributeMaxDynamicSharedMemorySize, smem_bytes);
    gemm_kernel<<<(M_TOTAL + BM - 1) / BM, 256, smem_bytes>>>(conv_b, out);
}

// round 3
// speedup vs baseline: 1.6474x; 1.6474x over previous
#include <cuda_runtime.h>
#include <cuda_bf16.h>
#include <cstdint>

#define N_PTS   10242
#define C_DIM   64
#define K_DIM   9
#define NBR_DIM 7
#define O_DIM   64
#define BT_DIM  16
#define M_TOTAL (BT_DIM * N_PTS)     /* 163872 */
#define CK_DIM  (C_DIM * K_DIM)      /* 576    */

#define BM       128
#define BK       32
#define N_CHUNKS (CK_DIM / BK)       /* 18 */
#define A_LDB    80                  /* smem row pitch in bytes (32 bf16 + 16B pad) */

// ---------------- scratch (static device arrays, no runtime alloc) ----------
__device__ __nv_bfloat16 g_Ahi[(size_t)M_TOTAL * CK_DIM];   // A hi, [m][k*64+c]
__device__ __nv_bfloat16 g_Alo[(size_t)M_TOTAL * CK_DIM];   // A lo
__device__ __nv_bfloat16 g_Whi[CK_DIM * O_DIM];             // W hi, [o][k*64+c]
__device__ __nv_bfloat16 g_Wlo[CK_DIM * O_DIM];             // W lo
__device__ int g_is64;

// ---------------- PTX helpers ----------------------------------------------
__device__ __forceinline__ uint32_t smem_u32(const void* p) {
    uint32_t a;
    asm("{ .reg .u64 t; cvta.to.shared.u64 t, %1; cvt.u32.u64 %0, t; }"
        : "=r"(a) : "l"(p));
    return a;
}

#define LDSM_X4(r, addr) \
    asm volatile("ldmatrix.sync.aligned.m8n8.x4.shared.b16 {%0,%1,%2,%3}, [%4];" \
        : "=r"((r)[0]), "=r"((r)[1]), "=r"((r)[2]), "=r"((r)[3]) : "r"(addr))

#define MMA_BF16(d, a, b0, b1) \
    asm volatile("mma.sync.aligned.m16n8k16.row.col.f32.bf16.bf16.f32 " \
        "{%0,%1,%2,%3}, {%4,%5,%6,%7}, {%8,%9}, {%0,%1,%2,%3};" \
        : "+f"((d)[0]), "+f"((d)[1]), "+f"((d)[2]), "+f"((d)[3]) \
        : "r"((a)[0]), "r"((a)[1]), "r"((a)[2]), "r"((a)[3]), "r"(b0), "r"(b1))

// ---------------- small setup kernels ---------------------------------------
__global__ void detect_idx_kernel(const int* __restrict__ idx32) {
    __shared__ int s_any;
    if (threadIdx.x == 0) s_any = 0;
    __syncthreads();
    int any = 0;
    const int pairs = N_PTS * NBR_DIM / 2;
    for (int i = threadIdx.x; i < pairs; i += blockDim.x)
        any |= (idx32[2 * i + 1] != 0);
    if (any) s_any = 1;
    __syncthreads();
    if (threadIdx.x == 0) g_is64 = (s_any == 0);
}

// W[o][cc] = conv_w[o, c, 0, k], split into bf16 hi/lo
__global__ void prepack_w_kernel(const float* __restrict__ conv_w) {
    int i = blockIdx.x * 256 + threadIdx.x;
    if (i >= CK_DIM * O_DIM) return;
    int o  = i / CK_DIM;
    int cc = i - o * CK_DIM;
    int k  = cc >> 6;
    int c  = cc & 63;
    float w = conv_w[(o * 64 + c) * 9 + k];
    __nv_bfloat16 hi = __float2bfloat16_rn(w);
    g_Whi[i] = hi;
    g_Wlo[i] = __float2bfloat16_rn(w - __bfloat162float(hi));
}

// ---------------- phase 1: interpolation -> split bf16 A --------------------
__global__ void interp_kernel(const float* __restrict__ x,
                              const void*  __restrict__ index_raw,
                              const float* __restrict__ itp_mat) {
    __shared__ float sT[4][NBR_DIM * K_DIM];
    __shared__ int   sIdx[4][NBR_DIM];
    const int tid = threadIdx.x;
    const int m0  = blockIdx.x * 4;
    const int is64 = g_is64;

    for (int i = tid; i < 4 * 63; i += 256) {
        int mi = i / 63, e = i - mi * 63;
        int n = (m0 + mi) % N_PTS;
        sT[mi][e] = itp_mat[n * 63 + e];
    }
    if (tid < 4 * NBR_DIM) {
        int mi = tid / NBR_DIM, j = tid - mi * NBR_DIM;
        int n = (m0 + mi) % N_PTS;
        int v;
        if (is64) v = (int)((const long long*)index_raw)[n * NBR_DIM + j];
        else      v = ((const int*)index_raw)[n * NBR_DIM + j];
        sIdx[mi][j] = v;
    }
    __syncthreads();

    const int c    = tid & 63;
    const int mloc = tid >> 6;
    const int m    = m0 + mloc;
    const int bt   = m / N_PTS;
    const float* xb = x + (size_t)bt * N_PTS * C_DIM;

    float acc[K_DIM];
#pragma unroll
    for (int k = 0; k < K_DIM; k++) acc[k] = 0.f;

#pragma unroll
    for (int j = 0; j < NBR_DIM; j++) {
        float v = __ldg(xb + (size_t)sIdx[mloc][j] * C_DIM + c);
        const float* tj = &sT[mloc][j * K_DIM];
#pragma unroll
        for (int k = 0; k < K_DIM; k++) acc[k] = fmaf(v, tj[k], acc[k]);
    }

    __nv_bfloat16* dh = g_Ahi + (size_t)m * CK_DIM + c;
    __nv_bfloat16* dl = g_Alo + (size_t)m * CK_DIM + c;
#pragma unroll
    for (int k = 0; k < K_DIM; k++) {
        float v = acc[k];
        __nv_bfloat16 hi = __float2bfloat16_rn(v);
        dh[k * 64] = hi;
        dl[k * 64] = __float2bfloat16_rn(v - __bfloat162float(hi));
    }
}

// ---------------- phase 2: HMMA bf16 GEMM (3-term split) --------------------
// Out[m,o] = sum_cc A[m,cc]*W[o,cc] + b[o]
// CTA: 128m x 64o, 18 K-chunks of 32. 8 warps: wm = wid&3 (32 rows),
// wn = wid>>2 (32 cols). Per warp: 2 m-subtiles x 4 o-subtiles of m16n8k16.
__global__ void __launch_bounds__(256, 2)
gemm_mma_kernel(const float* __restrict__ conv_b, float* __restrict__ out) {
    __shared__ uint8_t sAhi[BM * A_LDB];        // 10 KB
    __shared__ uint8_t sAlo[BM * A_LDB];        // 10 KB
    __shared__ uint8_t sWhi[O_DIM * A_LDB];     //  5 KB
    __shared__ uint8_t sWlo[O_DIM * A_LDB];     //  5 KB

    const int tid = threadIdx.x;
    const int wid = tid >> 5;
    const int lid = tid & 31;
    const int wm  = wid & 3;
    const int wn  = wid >> 2;
    const int m0  = blockIdx.x * BM;

    // per-lane ldmatrix offsets (bytes), before s/g/kstep adjustments
    // A: matrix j=lid>>3 -> row (j&1)*8 + (lid&7), col16B (j>>1)
    const uint32_t aFragOff =
        (uint32_t)((wm * 32 + ((lid >> 3) & 1) * 8 + (lid & 7)) * A_LDB
                   + (lid >> 4) * 16);
    // W: matrix j -> n-sub (j>>1)*8, koff (j&1)*16B
    const uint32_t wFragOff =
        (uint32_t)((wn * 32 + (lid >> 4) * 8 + (lid & 7)) * A_LDB
                   + ((lid >> 3) & 1) * 16);

    const uint32_t uAhi = smem_u32(sAhi);
    const uint32_t uAlo = smem_u32(sAlo);
    const uint32_t uWhi = smem_u32(sWhi);
    const uint32_t uWlo = smem_u32(sWlo);

    float acc[2][4][4];
#pragma unroll
    for (int s = 0; s < 2; s++)
#pragma unroll
        for (int n = 0; n < 4; n++)
#pragma unroll
            for (int q = 0; q < 4; q++) acc[s][n][q] = 0.f;

    // ---- gmem load indexing: A 512 16B-units / 256 thr = 2 each; W 1 each --
    const int aRow0 = tid >> 2;            // 0..63
    const int aU    = tid & 3;
    const char* pAhi = (const char*)g_Ahi;
    const char* pAlo = (const char*)g_Alo;
    const char* pWhi = (const char*)g_Whi;
    const char* pWlo = (const char*)g_Wlo;

    uint4 rAh[2], rAl[2], rWh, rWl;
    const uint4 Z4 = make_uint4(0, 0, 0, 0);

    // prefetch chunk 0
    {
        const int cc0B = 0;
#pragma unroll
        for (int i = 0; i < 2; i++) {
            int row = aRow0 + i * 64;
            int m = m0 + row;
            size_t off = (size_t)m * (CK_DIM * 2) + cc0B + aU * 16;
            rAh[i] = (m < M_TOTAL) ? *(const uint4*)(pAhi + off) : Z4;
            rAl[i] = (m < M_TOTAL) ? *(const uint4*)(pAlo + off) : Z4;
        }
        size_t woff = (size_t)(tid >> 2) * (CK_DIM * 2) + cc0B + aU * 16;
        rWh = *(const uint4*)(pWhi + woff);
        rWl = *(const uint4*)(pWlo + woff);
    }

    for (int ch = 0; ch < N_CHUNKS; ch++) {
        __syncthreads();   // previous chunk's LDSMs done
        // ---- STS ----
#pragma unroll
        for (int i = 0; i < 2; i++) {
            int row = aRow0 + i * 64;
            *(uint4*)(sAhi + row * A_LDB + aU * 16) = rAh[i];
            *(uint4*)(sAlo + row * A_LDB + aU * 16) = rAl[i];
        }
        *(uint4*)(sWhi + (tid >> 2) * A_LDB + aU * 16) = rWh;
        *(uint4*)(sWlo + (tid >> 2) * A_LDB + aU * 16) = rWl;
        __syncthreads();

        // ---- prefetch next chunk (overlaps HMMA below) ----
        if (ch + 1 < N_CHUNKS) {
            const int cc0B = (ch + 1) * BK * 2;
#pragma unroll
            for (int i = 0; i < 2; i++) {
                int row = aRow0 + i * 64;
                int m = m0 + row;
                size_t off = (size_t)m * (CK_DIM * 2) + cc0B + aU * 16;
                rAh[i] = (m < M_TOTAL) ? *(const uint4*)(pAhi + off) : Z4;
                rAl[i] = (m < M_TOTAL) ? *(const uint4*)(pAlo + off) : Z4;
            }
            size_t woff = (size_t)(tid >> 2) * (CK_DIM * 2) + cc0B + aU * 16;
            rWh = *(const uint4*)(pWhi + woff);
            rWl = *(const uint4*)(pWlo + woff);
        }

        // ---- compute: 2 k-steps of 16 ----
#pragma unroll
        for (int ks = 0; ks < 2; ks++) {
            const uint32_t kB = ks * 32;
            uint32_t ah[2][4], al[2][4], wh[2][4], wl[2][4];
#pragma unroll
            for (int s = 0; s < 2; s++) {
                LDSM_X4(ah[s], uAhi + aFragOff + s * 16 * A_LDB + kB);
                LDSM_X4(al[s], uAlo + aFragOff + s * 16 * A_LDB + kB);
            }
#pragma unroll
            for (int g = 0; g < 2; g++) {
                LDSM_X4(wh[g], uWhi + wFragOff + g * 16 * A_LDB + kB);
                LDSM_X4(wl[g], uWlo + wFragOff + g * 16 * A_LDB + kB);
            }
#pragma unroll
            for (int s = 0; s < 2; s++)
#pragma unroll
                for (int g = 0; g < 2; g++) {
                    MMA_BF16(acc[s][g * 2 + 0], ah[s], wh[g][0], wh[g][1]);
                    MMA_BF16(acc[s][g * 2 + 1], ah[s], wh[g][2], wh[g][3]);
                    MMA_BF16(acc[s][g * 2 + 0], al[s], wh[g][0], wh[g][1]);
                    MMA_BF16(acc[s][g * 2 + 1], al[s], wh[g][2], wh[g][3]);
                    MMA_BF16(acc[s][g * 2 + 0], ah[s], wl[g][0], wl[g][1]);
                    MMA_BF16(acc[s][g * 2 + 1], ah[s], wl[g][2], wl[g][3]);
                }
        }
    }

    // ---- epilogue: bias + store ----
    float bias[4][2];
#pragma unroll
    for (int n = 0; n < 4; n++) {
        int ob = wn * 32 + n * 8 + (lid & 3) * 2;
        bias[n][0] = __ldg(conv_b + ob);
        bias[n][1] = __ldg(conv_b + ob + 1);
    }
#pragma unroll
    for (int s = 0; s < 2; s++)
#pragma unroll
        for (int h = 0; h < 2; h++) {
            int m = m0 + wm * 32 + s * 16 + h * 8 + (lid >> 2);
            if (m < M_TOTAL) {
                float* op = out + (size_t)m * O_DIM + wn * 32 + (lid & 3) * 2;
#pragma unroll
                for (int n = 0; n < 4; n++) {
                    float2 v;
                    v.x = acc[s][n][h * 2 + 0] + bias[n][0];
                    v.y = acc[s][n][h * 2 + 1] + bias[n][1];
                    *(float2*)(op + n * 8) = v;
                }
            }
        }
}

// ---------------------------------------------------------------------------
extern "C" void kernel_launch(void* const* d_in, const int* in_sizes, int n_in,
                              void* d_out, int out_size) {
    const float* x       = (const float*)d_in[0];
    const void*  index   = d_in[1];
    const float* itp_mat = (const float*)d_in[2];
    const float* conv_w  = (const float*)d_in[3];
    const float* conv_b  = (const float*)d_in[4];
    float*       out     = (float*)d_out;

    detect_idx_kernel<<<1, 256>>>((const int*)index);
    prepack_w_kernel<<<(CK_DIM * O_DIM + 255) / 256, 256>>>(conv_w);
    interp_kernel<<<M_TOTAL / 4, 256>>>(x, index, itp_mat);
    gemm_mma_kernel<<<(M_TOTAL + BM - 1) / BM, 256>>>(conv_b, out);
}